// round 16
// baseline (speedup 1.0000x reference)
#include <cuda_runtime.h>
#include <cstdint>

#define NB   2
#define NS   2048
#define NE   1024
#define NH   16
#define HD   64
#define MTOK (NB * NS)      // 4096
#define NQKV (3 * NE)       // 3072

// Scratch (allocation-free rule: __device__ globals)
__device__ float g_qkv[(size_t)MTOK * NQKV];   // 48 MB
__device__ float g_ctx[(size_t)MTOK * NE];     // 16 MB

__device__ __forceinline__ uint32_t f2tf(float x) {
    uint32_t r;
    asm("cvt.rna.tf32.f32 %0, %1;" : "=r"(r) : "f"(x));
    return r;
}

__device__ __forceinline__ void mma_tf32(float* c, const uint32_t* a, const uint32_t* b) {
    asm volatile(
        "mma.sync.aligned.m16n8k8.row.col.f32.tf32.tf32.f32 "
        "{%0,%1,%2,%3}, {%4,%5,%6,%7}, {%8,%9}, {%0,%1,%2,%3};"
        : "+f"(c[0]), "+f"(c[1]), "+f"(c[2]), "+f"(c[3])
        : "r"(a[0]), "r"(a[1]), "r"(a[2]), "r"(a[3]),
          "r"(b[0]), "r"(b[1]));
}

__device__ __forceinline__ void ldsm_x4(uint32_t* r, uint32_t addr) {
    asm volatile(
        "ldmatrix.sync.aligned.m8n8.x4.shared.b16 {%0,%1,%2,%3}, [%4];"
        : "=r"(r[0]), "=r"(r[1]), "=r"(r[2]), "=r"(r[3]) : "r"(addr));
}

// ---------------------------------------------------------------------------
// GEMM: C[M,N] = A[M,K] @ B[N,K]^T + bias[N]  via tf32 mma.sync.m16n8k8
// (R10 structure: 4 warps 64x64 warp tiles, ldmatrix.x4 frag loads,
//  natural-layout smem stride 12, double-buffered.)
// ---------------------------------------------------------------------------
#define AST 12                      // words per smem row (8 data + 4 pad)
#define GBUF (128 * AST)            // words per tile buffer (= 6144 B)

__device__ __forceinline__ void gemm_body(const float* __restrict__ A,
                                          const float* __restrict__ B,
                                          const float* __restrict__ bias,
                                          float* __restrict__ C,
                                          int N, int K)
{
    __shared__ __align__(16) uint32_t As[2][GBUF];
    __shared__ __align__(16) uint32_t Bs[2][GBUF];

    const int tid  = threadIdx.x;        // 0..127
    const int warp = tid >> 5;           // 0..3
    const int lane = tid & 31;
    const int wm   = warp >> 1;          // 0..1 -> 64-row band
    const int wn   = warp & 1;           // 0..1 -> 64-col band
    const int grp  = lane >> 2;
    const int qid  = lane & 3;
    const int mBase = blockIdx.y * 128;
    const int nBase = blockIdx.x * 128;

    // ldmatrix addresses (lane-dependent, buffer 0)
    const int lj = lane >> 3;            // matrix index 0..3
    const int li = lane & 7;             // row within matrix
    const uint32_t asBase = (uint32_t)__cvta_generic_to_shared(&As[0][0]);
    const uint32_t bsBase = (uint32_t)__cvta_generic_to_shared(&Bs[0][0]);
    // A: matrix j -> rows +(j&1)*8, cols (j>>1)*4
    const uint32_t aAddr0 = asBase +
        (((wm * 64 + (lj & 1) * 8 + li) * AST + (lj >> 1) * 4) << 2);
    // B: matrix j -> rows +(j>>1)*8, cols (j&1)*4
    const uint32_t bAddr0 = bsBase +
        (((wn * 64 + (lj >> 1) * 8 + li) * AST + (lj & 1) * 4) << 2);

    float acc[4][8][4];
#pragma unroll
    for (int mt = 0; mt < 4; mt++)
#pragma unroll
        for (int nt = 0; nt < 8; nt++)
#pragma unroll
            for (int j = 0; j < 4; j++) acc[mt][nt][j] = 0.0f;

    // loader: thread t owns A row t and B row t (8 k-words each, 2 x uint4)
    const float* Ap = A + (size_t)(mBase + tid) * K;
    const float* Bp = B + (size_t)(nBase + tid) * K;

    const int T = K / 8;

    {
        float4 a0 = *(const float4*)(Ap);
        float4 a1 = *(const float4*)(Ap + 4);
        float4 b0 = *(const float4*)(Bp);
        float4 b1 = *(const float4*)(Bp + 4);
        uint4 ta0 = make_uint4(f2tf(a0.x), f2tf(a0.y), f2tf(a0.z), f2tf(a0.w));
        uint4 ta1 = make_uint4(f2tf(a1.x), f2tf(a1.y), f2tf(a1.z), f2tf(a1.w));
        uint4 tb0 = make_uint4(f2tf(b0.x), f2tf(b0.y), f2tf(b0.z), f2tf(b0.w));
        uint4 tb1 = make_uint4(f2tf(b1.x), f2tf(b1.y), f2tf(b1.z), f2tf(b1.w));
        *(uint4*)&As[0][tid * AST]     = ta0;
        *(uint4*)&As[0][tid * AST + 4] = ta1;
        *(uint4*)&Bs[0][tid * AST]     = tb0;
        *(uint4*)&Bs[0][tid * AST + 4] = tb1;
    }
    __syncthreads();

    int buf = 0;
    for (int t = 0; t < T; t++) {
        float4 a0n, a1n, b0n, b1n;
        const bool more = (t + 1 < T);
        if (more) {
            a0n = *(const float4*)(Ap + (t + 1) * 8);
            a1n = *(const float4*)(Ap + (t + 1) * 8 + 4);
            b0n = *(const float4*)(Bp + (t + 1) * 8);
            b1n = *(const float4*)(Bp + (t + 1) * 8 + 4);
        }

        // ---- fragment loads via ldmatrix ----
        const uint32_t bufOff = (uint32_t)buf * (GBUF * 4);
        uint32_t af[4][4];                  // [mt] -> a0..a3
#pragma unroll
        for (int mt = 0; mt < 4; mt++)
            ldsm_x4(af[mt], aAddr0 + bufOff + mt * (16 * AST * 4));
        uint32_t bf[4][4];                  // [np]: r0,r1 = n-tile 2np; r2,r3 = 2np+1
#pragma unroll
        for (int np = 0; np < 4; np++)
            ldsm_x4(bf[np], bAddr0 + bufOff + np * (16 * AST * 4));

        // ---- 32 mma ----
#pragma unroll
        for (int mt = 0; mt < 4; mt++)
#pragma unroll
            for (int nt = 0; nt < 8; nt++)
                mma_tf32(acc[mt][nt], af[mt], &bf[nt >> 1][(nt & 1) * 2]);

        if (more) {
            int nb = buf ^ 1;
            uint4 ta0 = make_uint4(f2tf(a0n.x), f2tf(a0n.y), f2tf(a0n.z), f2tf(a0n.w));
            uint4 ta1 = make_uint4(f2tf(a1n.x), f2tf(a1n.y), f2tf(a1n.z), f2tf(a1n.w));
            uint4 tb0 = make_uint4(f2tf(b0n.x), f2tf(b0n.y), f2tf(b0n.z), f2tf(b0n.w));
            uint4 tb1 = make_uint4(f2tf(b1n.x), f2tf(b1n.y), f2tf(b1n.z), f2tf(b1n.w));
            *(uint4*)&As[nb][tid * AST]     = ta0;
            *(uint4*)&As[nb][tid * AST + 4] = ta1;
            *(uint4*)&Bs[nb][tid * AST]     = tb0;
            *(uint4*)&Bs[nb][tid * AST + 4] = tb1;
            __syncthreads();
            buf = nb;
        }
    }

    // ---- epilogue: bias + store (mma C layout) ----
#pragma unroll
    for (int nt = 0; nt < 8; nt++) {
        int col = nBase + wn * 64 + nt * 8 + 2 * qid;
        float2 b2 = *(const float2*)&bias[col];
#pragma unroll
        for (int mt = 0; mt < 4; mt++) {
            int row0 = mBase + wm * 64 + mt * 16 + grp;
            float2 o0, o1;
            o0.x = acc[mt][nt][0] + b2.x;
            o0.y = acc[mt][nt][1] + b2.y;
            o1.x = acc[mt][nt][2] + b2.x;
            o1.y = acc[mt][nt][3] + b2.y;
            *(float2*)&C[(size_t)row0 * N + col]       = o0;
            *(float2*)&C[(size_t)(row0 + 8) * N + col] = o1;
        }
    }
}

__global__ __launch_bounds__(128, 2) void gemm_qkv_kernel(
    const float* __restrict__ x, const float* __restrict__ w,
    const float* __restrict__ bias)
{
    gemm_body(x, w, bias, g_qkv, NQKV, NE);
}

__global__ __launch_bounds__(128, 2) void gemm_out_kernel(
    const float* __restrict__ w, const float* __restrict__ bias,
    float* __restrict__ out)
{
    gemm_body(g_ctx, w, bias, out, NE, NE);
}

// ---------------------------------------------------------------------------
// Flash attention, tf32 tensor cores, causal. BQ=128, BKV=64, HD=64.
// R14: S-phase Q/K and PV-phase P fragment loads converted to ldmatrix.x4
// (same derivation as the GEMM; V loads stay scalar — transposed A operand).
// Per-iter L1 ops/warp: ~352 -> ~208.
// ---------------------------------------------------------------------------
#define FBQ 128
#define FBK 64
#define QS_S 68
#define KS_S 76
#define VS_S 76
#define PS_S 68
#define QS_W (FBQ * QS_S)
#define KS_W (FBK * KS_S)
#define VS_W (FBK * VS_S)
#define PS_W (FBQ * PS_S)
#define FL_SMEM_W (QS_W + KS_W + VS_W + PS_W + FBQ)   // 27264 words = 109056 B

__global__ __launch_bounds__(256, 2) void flash_attn_kernel()
{
    extern __shared__ __align__(16) uint32_t fsm[];
    uint32_t* Qs = fsm;                 // [q=128][68]  (d cols)
    uint32_t* Ks = Qs + QS_W;           // [kv=64][76]  (d cols)
    uint32_t* Vs = Ks + KS_W;           // [kv=64][76]  (d cols)
    uint32_t* Ps = Vs + VS_W;           // [q=128][68]  (kv cols)
    float*    Al = (float*)(Ps + PS_W); // [128] per-q alpha / inv-l (warp-private slices)

    const int tid  = threadIdx.x;
    const int warp = tid >> 5;
    const int lane = tid & 31;
    const int grp  = lane >> 2;
    const int qid  = lane & 3;
    const int bh   = blockIdx.y;
    const int b    = bh >> 4;
    const int h    = bh & 15;
    const int qb   = (int)gridDim.x - 1 - (int)blockIdx.x;  // long blocks first
    const int tokBase = b * NS + qb * FBQ;
    const int qw      = warp * 16;                 // warp's first q row (local)
    const float* qkv  = g_qkv;

    // ldmatrix shared-window addresses (same quadrant maps as gemm_body)
    const int lj = lane >> 3;
    const int li = lane & 7;
    const uint32_t smemBase = (uint32_t)__cvta_generic_to_shared(fsm);
    // Q as A-frag: matrix j -> rows +(j&1)*8, cols (j>>1)*4
    const uint32_t qAddrS = smemBase +
        (((qw + (lj & 1) * 8 + li) * QS_S + (lj >> 1) * 4) << 2);
    // K as B-frag: matrix j -> rows +(j>>1)*8, cols (j&1)*4
    const uint32_t kAddrS = smemBase + QS_W * 4 +
        ((((lj >> 1) * 8 + li) * KS_S + (lj & 1) * 4) << 2);
    // P as B-frag (warp's 16 q rows)
    const uint32_t pAddrS = smemBase + (QS_W + KS_W + VS_W) * 4 +
        (((qw + (lj >> 1) * 8 + li) * PS_S + (lj & 1) * 4) << 2);

    // ---- load Q block, pre-scaled, tf32, natural [q][d] ----
#pragma unroll
    for (int i = 0; i < 8; i++) {
        int u  = tid + i * 256;
        int r  = u >> 4;
        int c4 = (u & 15) * 4;
        float4 v = *(const float4*)(qkv + (size_t)(tokBase + r) * NQKV + h * HD + c4);
        uint4 t;
        t.x = f2tf(v.x * 0.125f); t.y = f2tf(v.y * 0.125f);
        t.z = f2tf(v.z * 0.125f); t.w = f2tf(v.w * 0.125f);
        *(uint4*)&Qs[r * QS_S + c4] = t;
    }

    float O[4][2][4];     // [mt(d)][nt(q)][j]  (transposed frags)
    float m_i[2], l_i[2];
    m_i[0] = m_i[1] = -1e30f;
    l_i[0] = l_i[1] = 0.0f;
#pragma unroll
    for (int mt = 0; mt < 4; mt++)
#pragma unroll
        for (int nt = 0; nt < 2; nt++)
#pragma unroll
            for (int j = 0; j < 4; j++) O[mt][nt][j] = 0.0f;

    const int nkb = 2 * qb + 2;
    for (int kb = 0; kb < nkb; kb++) {
        __syncthreads();   // protect Ks/Vs from previous iteration's PV reads

        // ---- load K, V tiles (natural layouts, tf32) ----
#pragma unroll
        for (int i = 0; i < 4; i++) {
            int u  = tid + i * 256;
            int r  = u >> 4;
            int c4 = (u & 15) * 4;
            const float* base = qkv + (size_t)(b * NS + kb * FBK + r) * NQKV + h * HD;
            float4 kv4 = *(const float4*)(base + NE + c4);
            float4 vv4 = *(const float4*)(base + 2 * NE + c4);
            uint4 tk, tv;
            tk.x = f2tf(kv4.x); tk.y = f2tf(kv4.y); tk.z = f2tf(kv4.z); tk.w = f2tf(kv4.w);
            tv.x = f2tf(vv4.x); tv.y = f2tf(vv4.y); tv.z = f2tf(vv4.z); tv.w = f2tf(vv4.w);
            *(uint4*)&Ks[r * KS_S + c4] = tk;
            *(uint4*)&Vs[r * VS_S + c4] = tv;
        }
        __syncthreads();

        // warp has any unmasked kv in this block?
        const bool active = (kb * FBK) <= (qb * FBQ + qw + 15);

        if (active) {
            // ---- S = Q @ K^T  (ldmatrix frag loads) ----
            float s[8][4];
#pragma unroll
            for (int nt = 0; nt < 8; nt++)
#pragma unroll
                for (int j = 0; j < 4; j++) s[nt][j] = 0.0f;

#pragma unroll
            for (int ks = 0; ks < 8; ks++) {
                uint32_t a[4];
                ldsm_x4(a, qAddrS + ks * 32);
#pragma unroll
                for (int np = 0; np < 4; np++) {
                    uint32_t bnp[4];
                    ldsm_x4(bnp, kAddrS + np * (16 * KS_S * 4) + ks * 32);
                    mma_tf32(s[2 * np],     a, &bnp[0]);
                    mma_tf32(s[2 * np + 1], a, &bnp[2]);
                }
            }

            // ---- causal mask ----
            const int row0 = qb * FBQ + qw + grp;     // global q rows
            const int row1 = row0 + 8;
            const int colB = kb * FBK;
            if (colB + FBK - 1 > row0) {
#pragma unroll
                for (int nt = 0; nt < 8; nt++) {
                    int col = colB + nt * 8 + 2 * qid;
                    if (col     > row0) s[nt][0] = -1e30f;
                    if (col + 1 > row0) s[nt][1] = -1e30f;
                    if (col     > row1) s[nt][2] = -1e30f;
                    if (col + 1 > row1) s[nt][3] = -1e30f;
                }
            }

            // ---- online softmax (per row-half, quad reduction) ----
#pragma unroll
            for (int hf = 0; hf < 2; hf++) {
                const int j0 = 2 * hf;
                float rmax = s[0][j0];
#pragma unroll
                for (int nt = 0; nt < 8; nt++) {
                    rmax = fmaxf(rmax, s[nt][j0]);
                    rmax = fmaxf(rmax, s[nt][j0 + 1]);
                }
                rmax = fmaxf(rmax, __shfl_xor_sync(0xffffffffu, rmax, 1));
                rmax = fmaxf(rmax, __shfl_xor_sync(0xffffffffu, rmax, 2));

                float mnew  = fmaxf(m_i[hf], rmax);
                float alpha = __expf(m_i[hf] - mnew);
                float lsum  = 0.0f;
#pragma unroll
                for (int nt = 0; nt < 8; nt++) {
                    float p0 = __expf(s[nt][j0]     - mnew);
                    float p1 = __expf(s[nt][j0 + 1] - mnew);
                    s[nt][j0] = p0; s[nt][j0 + 1] = p1;
                    lsum += p0 + p1;
                }
                lsum += __shfl_xor_sync(0xffffffffu, lsum, 1);
                lsum += __shfl_xor_sync(0xffffffffu, lsum, 2);

                l_i[hf] = l_i[hf] * alpha + lsum;
                m_i[hf] = mnew;
                if (qid == 0) Al[qw + grp + hf * 8] = alpha;
            }

            // ---- write P (tf32) to Ps[q][kv] ----
#pragma unroll
            for (int nt = 0; nt < 8; nt++) {
                uint2 p0, p1;
                p0.x = f2tf(s[nt][0]); p0.y = f2tf(s[nt][1]);
                p1.x = f2tf(s[nt][2]); p1.y = f2tf(s[nt][3]);
                *(uint2*)&Ps[(qw + grp)     * PS_S + nt * 8 + 2 * qid] = p0;
                *(uint2*)&Ps[(qw + grp + 8) * PS_S + nt * 8 + 2 * qid] = p1;
            }
        }
        __syncwarp();

        if (active) {
            // ---- rescale O by per-q alpha ----
            float av[2][2];
#pragma unroll
            for (int nt = 0; nt < 2; nt++) {
                av[nt][0] = Al[qw + nt * 8 + 2 * qid];
                av[nt][1] = Al[qw + nt * 8 + 2 * qid + 1];
            }
#pragma unroll
            for (int mt = 0; mt < 4; mt++)
#pragma unroll
                for (int nt = 0; nt < 2; nt++) {
                    O[mt][nt][0] *= av[nt][0];
                    O[mt][nt][1] *= av[nt][1];
                    O[mt][nt][2] *= av[nt][0];
                    O[mt][nt][3] *= av[nt][1];
                }

            // ---- O^T += V^T @ P^T  (A = Vs scalar, B = Ps via ldmatrix) ----
#pragma unroll
            for (int ks = 0; ks < 8; ks++) {
                uint32_t bp[4];
                ldsm_x4(bp, pAddrS + ks * 32);
#pragma unroll
                for (int mt = 0; mt < 4; mt++) {
                    uint32_t a[4];
                    a[0] = Vs[(ks * 8 + qid)     * VS_S + mt * 16 + grp];
                    a[1] = Vs[(ks * 8 + qid)     * VS_S + mt * 16 + grp + 8];
                    a[2] = Vs[(ks * 8 + qid + 4) * VS_S + mt * 16 + grp];
                    a[3] = Vs[(ks * 8 + qid + 4) * VS_S + mt * 16 + grp + 8];
                    mma_tf32(O[mt][0], a, &bp[0]);
                    mma_tf32(O[mt][1], a, &bp[2]);
                }
            }
        }
    }

    // ---- publish 1/l per q (warp-private Al slice), normalize + store ----
    if (qid == 0) {
        Al[qw + grp]     = 1.0f / l_i[0];
        Al[qw + grp + 8] = 1.0f / l_i[1];
    }
    __syncwarp();

    float iv[2][2];
#pragma unroll
    for (int nt = 0; nt < 2; nt++) {
        iv[nt][0] = Al[qw + nt * 8 + 2 * qid];
        iv[nt][1] = Al[qw + nt * 8 + 2 * qid + 1];
    }
#pragma unroll
    for (int mt = 0; mt < 4; mt++)
#pragma unroll
        for (int nt = 0; nt < 2; nt++) {
            int q = tokBase + qw + nt * 8 + 2 * qid;     // global token row
            int d = h * HD + mt * 16 + grp;
            g_ctx[(size_t)q       * NE + d]     = O[mt][nt][0] * iv[nt][0];
            g_ctx[(size_t)(q + 1) * NE + d]     = O[mt][nt][1] * iv[nt][1];
            g_ctx[(size_t)q       * NE + d + 8] = O[mt][nt][2] * iv[nt][0];
            g_ctx[(size_t)(q + 1) * NE + d + 8] = O[mt][nt][3] * iv[nt][1];
        }
}

// ---------------------------------------------------------------------------
extern "C" void kernel_launch(void* const* d_in, const int* in_sizes, int n_in,
                              void* d_out, int out_size)
{
    const float* x     = (const float*)d_in[0];
    const float* qkv_w = (const float*)d_in[1];
    const float* qkv_b = (const float*)d_in[2];
    const float* out_w = (const float*)d_in[3];
    const float* out_b = (const float*)d_in[4];
    float* out = (float*)d_out;

    const int flash_smem = FL_SMEM_W * (int)sizeof(uint32_t);   // 109,056 B
    cudaFuncSetAttribute(flash_attn_kernel,
                         cudaFuncAttributeMaxDynamicSharedMemorySize, flash_smem);

    // 1) QKV projection (tf32 tensor cores, ldmatrix frag loads)
    gemm_qkv_kernel<<<dim3(NQKV / 128, MTOK / 128), dim3(128)>>>(x, qkv_w, qkv_b);
    // 2) causal flash attention per (b, h) (tf32 + ldmatrix)
    flash_attn_kernel<<<dim3(NS / FBQ, NB * NH), dim3(256), flash_smem>>>();
    // 3) output projection (tf32 tensor cores, ldmatrix frag loads)
    gemm_out_kernel<<<dim3(NE / 128, MTOK / 128), dim3(128)>>>(out_w, out_b, out);
}